// round 7
// baseline (speedup 1.0000x reference)
#include <cuda_runtime.h>

#define BATCH  32768
#define SEQT   28
#define DIMI   32
#define HH     32
#define NSTEPS 10

// MUFU.EX2-based transcendentals (~1e-7 rel err)
__device__ __forceinline__ float fast_tanh(float x) {
    float e = __expf(2.0f * x);
    return 1.0f - __fdividef(2.0f, e + 1.0f);
}
__device__ __forceinline__ float fast_sigmoid(float x) {
    return __fdividef(1.0f, 1.0f + __expf(-x));
}

struct __align__(16) SW {
    float W1[HH * HH];
    float W2[HH * HH];
    float b1[HH];
    float b2[HH];
    float Wih[3 * HH * DIMI];
    float Whh[3 * HH * HH];
    float bih[3 * HH];
    float bhh[3 * HH];
};

// 4-lane split matvec. Lane sub-index q = lane&3 owns input slice k in
// [8q, 8q+8) (passed in v[8]) and produces partials for ALL 32 outputs,
// grouped by XOR: pg[g*8+i] = partial of output j = 8*(q^g)+i over own k.
// Register indices are lane-uniform; laneness lives only in addresses.
template <bool ACC>
__device__ __forceinline__ void matvec4(const float* __restrict__ v,
                                        const float* __restrict__ Wbase,
                                        int q,
                                        float* __restrict__ pg) {
#pragma unroll
    for (int g = 0; g < 4; g++) {
        const float* rb = Wbase + (8 * (q ^ g)) * HH + 8 * q;
#pragma unroll
        for (int i = 0; i < 8; i++) {
            const float4* r = (const float4*)(rb + i * HH);
            float4 w0 = r[0];
            float4 w1 = r[1];
            float s;
            s = v[0] * w0.x;
            s = fmaf(v[1], w0.y, s);
            s = fmaf(v[2], w0.z, s);
            s = fmaf(v[3], w0.w, s);
            s = fmaf(v[4], w1.x, s);
            s = fmaf(v[5], w1.y, s);
            s = fmaf(v[6], w1.z, s);
            s = fmaf(v[7], w1.w, s);
            if (ACC) pg[g * 8 + i] += s;
            else     pg[g * 8 + i] = s;
        }
    }
}

// Butterfly reduce: out[i] = full dot of output j = 8q+i.
// Stage 1 (xor 1) merges k-halves within lane pairs; stage 2 (xor 2) finishes.
__device__ __forceinline__ void reduce4(const float* __restrict__ pg,
                                        float* __restrict__ out) {
#pragma unroll
    for (int i = 0; i < 8; i++) {
        float s0 = pg[i]      + __shfl_xor_sync(0xffffffffu, pg[8 + i],  1);
        float s2 = pg[16 + i] + __shfl_xor_sync(0xffffffffu, pg[24 + i], 1);
        out[i] = s0 + __shfl_xor_sync(0xffffffffu, s2, 2);
    }
}

// ---------- RK4 over one span ----------
__device__ __forceinline__ void rk4(float* __restrict__ y, float dt, int q,
                                    const SW& s) {
    const float dt6 = dt * (1.0f / 6.0f);
    const float dt3 = dt * (1.0f / 3.0f);
    const float dth = dt * 0.5f;
    const float* b1q = s.b1 + 8 * q;
    const float* b2q = s.b2 + 8 * q;
#pragma unroll 1
    for (int st = 0; st < NSTEPS; st++) {
        float acc[8], yt[8];
#pragma unroll
        for (int i = 0; i < 8; i++) { acc[i] = y[i]; yt[i] = y[i]; }
#pragma unroll 1
        for (int sidx = 0; sidx < 4; sidx++) {
            const float ca = (sidx == 1 || sidx == 2) ? dt3 : dt6;
            const float cy = (sidx >= 2) ? dt : dth;
            float pg[32], t[8];
            matvec4<false>(yt, s.W1, q, pg);
            reduce4(pg, t);
#pragma unroll
            for (int i = 0; i < 8; i++)
                t[i] = fast_tanh(t[i] + b1q[i]);
            matvec4<false>(t, s.W2, q, pg);
            reduce4(pg, t);                     // t now holds k-stage value
#pragma unroll
            for (int i = 0; i < 8; i++) {
                float kk = t[i] + b2q[i];
                acc[i] = fmaf(ca, kk, acc[i]);
                yt[i]  = fmaf(cy, kk, y[i]);    // dead at sidx==3
            }
        }
#pragma unroll
        for (int i = 0; i < 8; i++) y[i] = acc[i];
    }
}

// ---------- GRU cell (PyTorch gate order r,z,n) ----------
__device__ __forceinline__ void gru(float* __restrict__ h,
                                    const float* __restrict__ xg,
                                    int q, const SW& s) {
    float x[8];
    {
        const float4* x4 = (const float4*)xg;
        float4 v0 = x4[0], v1 = x4[1];
        x[0] = v0.x; x[1] = v0.y; x[2] = v0.z; x[3] = v0.w;
        x[4] = v1.x; x[5] = v1.y; x[6] = v1.z; x[7] = v1.w;
    }
    const int q8 = 8 * q;
    float pg[32], r[8], z[8];

    // r gate: accumulate x- and h-matvec partials, one reduction
    matvec4<false>(x, s.Wih, q, pg);
    matvec4<true>(h, s.Whh, q, pg);
    reduce4(pg, r);
#pragma unroll
    for (int i = 0; i < 8; i++)
        r[i] = fast_sigmoid(r[i] + s.bih[q8 + i] + s.bhh[q8 + i]);

    // z gate
    matvec4<false>(x, s.Wih + HH * DIMI, q, pg);
    matvec4<true>(h, s.Whh + HH * HH, q, pg);
    reduce4(pg, z);
#pragma unroll
    for (int i = 0; i < 8; i++)
        z[i] = fast_sigmoid(z[i] + s.bih[HH + q8 + i] + s.bhh[HH + q8 + i]);

    // n gate: gi and gh separate (r scales only the h-path)
    float gi[8], gh[8];
    matvec4<false>(x, s.Wih + 2 * HH * DIMI, q, pg);
    reduce4(pg, gi);
    matvec4<false>(h, s.Whh + 2 * HH * HH, q, pg);
    reduce4(pg, gh);
#pragma unroll
    for (int i = 0; i < 8; i++) {
        float hn = gh[i] + s.bhh[2 * HH + q8 + i];
        float n  = fast_tanh(gi[i] + s.bih[2 * HH + q8 + i] + r[i] * hn);
        h[i] = (1.0f - z[i]) * n + z[i] * h[i];
    }
}

__device__ __forceinline__ void store_relu(float* __restrict__ dst,
                                           const float* __restrict__ y) {
    float4* d4 = (float4*)dst;
    d4[0] = make_float4(fmaxf(y[0], 0.0f), fmaxf(y[1], 0.0f),
                        fmaxf(y[2], 0.0f), fmaxf(y[3], 0.0f));
    d4[1] = make_float4(fmaxf(y[4], 0.0f), fmaxf(y[5], 0.0f),
                        fmaxf(y[6], 0.0f), fmaxf(y[7], 0.0f));
}

__global__ void __launch_bounds__(128) ode_gru_kernel(
    const float* __restrict__ inputs,   // [B, 28, 32]
    const float* __restrict__ h0,       // [B, 32]
    const float* __restrict__ Wih, const float* __restrict__ Whh,
    const float* __restrict__ bih, const float* __restrict__ bhh,
    const float* __restrict__ W1,  const float* __restrict__ b1,
    const float* __restrict__ W2,  const float* __restrict__ b2,
    float* __restrict__ out)            // [2, B, 32]
{
    __shared__ SW s;
    const int tid = threadIdx.x;

    for (int i = tid; i < HH * HH; i += 128) { s.W1[i] = W1[i]; s.W2[i] = W2[i]; }
    for (int i = tid; i < 3 * HH * DIMI; i += 128) { s.Wih[i] = Wih[i]; s.Whh[i] = Whh[i]; }
    if (tid < HH)     { s.b1[tid]  = b1[tid];  s.b2[tid]  = b2[tid]; }
    if (tid < 3 * HH) { s.bih[tid] = bih[tid]; s.bhh[tid] = bhh[tid]; }
    __syncthreads();

    const int gt  = blockIdx.x * 128 + tid;  // 4 lanes per batch row
    const int row = gt >> 2;
    const int q   = gt & 3;                  // lane's slice index, elems [8q,8q+8)

    float y[8];
    {
        const float4* h04 = (const float4*)(h0 + (size_t)row * HH + 8 * q);
        float4 v0 = h04[0], v1 = h04[1];
        y[0] = v0.x; y[1] = v0.y; y[2] = v0.z; y[3] = v0.w;
        y[4] = v1.x; y[5] = v1.y; y[6] = v1.z; y[7] = v1.w;
    }

    const float* xbase = inputs + (size_t)row * SEQT * DIMI + 8 * q;

    rk4(y, 0.1f, q, s);                           // initial span [0,1]
#pragma unroll 1
    for (int t = 0; t < SEQT - 1; t++) {          // steps 0..26
        gru(y, xbase + t * DIMI, q, s);
        rk4(y, 0.1f, q, s);
    }
    // step 27: GRU -> h_start, then span-14 integration -> h_end
    gru(y, xbase + (SEQT - 1) * DIMI, q, s);
    store_relu(out + (size_t)row * HH + 8 * q, y);
    rk4(y, 1.4f, q, s);
    store_relu(out + ((size_t)BATCH + row) * HH + 8 * q, y);
}

extern "C" void kernel_launch(void* const* d_in, const int* in_sizes, int n_in,
                              void* d_out, int out_size) {
    (void)in_sizes; (void)n_in; (void)out_size;
    ode_gru_kernel<<<(4 * BATCH) / 128, 128>>>(
        (const float*)d_in[0], (const float*)d_in[1],
        (const float*)d_in[2], (const float*)d_in[3],
        (const float*)d_in[4], (const float*)d_in[5],
        (const float*)d_in[6], (const float*)d_in[7],
        (const float*)d_in[8], (const float*)d_in[9],
        (float*)d_out);
}

// round 8
// speedup vs baseline: 3.6009x; 3.6009x over previous
#include <cuda_runtime.h>

#define BATCH  32768
#define SEQT   28
#define DIMI   32
#define HH     32
#define NSTEPS 10

// MUFU.EX2-based transcendentals (~1e-7 rel err)
__device__ __forceinline__ float fast_tanh(float x) {
    float e = __expf(2.0f * x);
    return 1.0f - __fdividef(2.0f, e + 1.0f);
}
__device__ __forceinline__ float fast_sigmoid(float x) {
    return __fdividef(1.0f, 1.0f + __expf(-x));
}

struct __align__(16) SW {
    float W1[HH * HH];
    float W2[HH * HH];
    float b1[HH];
    float b2[HH];
    float Wih[3 * HH * DIMI];
    float Whh[3 * HH * HH];
    float bih[3 * HH];
    float bhh[3 * HH];
};

// Partial matvec: v = this lane's 16 input elems (k in [q16, q16+16)).
//   pA[i] (+)= sum_k v_k * W[q16+i][k]        (own j-half)
//   pB[i] (+)= sum_k v_k * W[(16-q16)+i][k]   (partner's j-half)
// NOTE: unroll 4 on the i-loop is deliberate — full unroll makes ptxas
// front-batch up to 32 LDS.128 results and balloon register allocation.
template <bool ACC>
__device__ __forceinline__ void matvec_half(const float* __restrict__ v,
                                            const float* __restrict__ Wbase,
                                            int q16,
                                            float* __restrict__ pA,
                                            float* __restrict__ pB) {
    const int jB = 16 - q16;
#pragma unroll 4
    for (int i = 0; i < 16; i++) {
        const float4* rA = (const float4*)(Wbase + (q16 + i) * HH + q16);
        const float4* rB = (const float4*)(Wbase + (jB + i) * HH + q16);
        float sA = 0.0f, sB = 0.0f;
#pragma unroll
        for (int c = 0; c < 4; c++) {
            float4 wa = rA[c];
            float4 wb = rB[c];
            sA = fmaf(v[4 * c + 0], wa.x, sA);
            sA = fmaf(v[4 * c + 1], wa.y, sA);
            sA = fmaf(v[4 * c + 2], wa.z, sA);
            sA = fmaf(v[4 * c + 3], wa.w, sA);
            sB = fmaf(v[4 * c + 0], wb.x, sB);
            sB = fmaf(v[4 * c + 1], wb.y, sB);
            sB = fmaf(v[4 * c + 2], wb.z, sB);
            sB = fmaf(v[4 * c + 3], wb.w, sB);
        }
        if (ACC) { pA[i] += sA; pB[i] += sB; }
        else     { pA[i] = sA;  pB[i] = sB; }
    }
}

// full dot for own j-half = own partial + partner's cross partial (+ bias row)
#define COMBINE_BIAS(dst, pA, pB, brow)                                   \
    _Pragma("unroll")                                                     \
    for (int i = 0; i < 16; i++)                                          \
        dst[i] = pA[i] + __shfl_xor_sync(0xffffffffu, pB[i], 1) + (brow)[i];

// ---------- RK4 over one span ----------
__device__ __forceinline__ void rk4(float* __restrict__ y, float dt, int q16,
                                    const SW& s) {
    const float dt6 = dt * (1.0f / 6.0f);
    const float dt3 = dt * (1.0f / 3.0f);
    const float dth = dt * 0.5f;
    const float* b1q = s.b1 + q16;
    const float* b2q = s.b2 + q16;
#pragma unroll 1
    for (int st = 0; st < NSTEPS; st++) {
        float acc[16], yt[16];
#pragma unroll
        for (int i = 0; i < 16; i++) { acc[i] = y[i]; yt[i] = y[i]; }
#pragma unroll 1
        for (int sidx = 0; sidx < 4; sidx++) {
            const float ca = (sidx == 1 || sidx == 2) ? dt3 : dt6;
            const float cy = (sidx >= 2) ? dt : dth;
            float pA[16], pB[16], t[16];
            matvec_half<false>(yt, s.W1, q16, pA, pB);
            COMBINE_BIAS(t, pA, pB, b1q);
#pragma unroll
            for (int i = 0; i < 16; i++)
                t[i] = fast_tanh(t[i]);
            matvec_half<false>(t, s.W2, q16, pA, pB);
            COMBINE_BIAS(t, pA, pB, b2q);      // t now holds k-stage value
#pragma unroll
            for (int i = 0; i < 16; i++) {
                acc[i] = fmaf(ca, t[i], acc[i]);
                yt[i]  = fmaf(cy, t[i], y[i]);   // dead at sidx==3
            }
        }
#pragma unroll
        for (int i = 0; i < 16; i++) y[i] = acc[i];
    }
}

// ---------- GRU cell (PyTorch gate order r,z,n) ----------
__device__ __forceinline__ void gru(float* __restrict__ h,
                                    const float* __restrict__ xg,
                                    int q16, const SW& s) {
    float x[16];
    const float4* x4 = (const float4*)xg;
#pragma unroll
    for (int c = 0; c < 4; c++) {
        float4 v = x4[c];
        x[4 * c] = v.x; x[4 * c + 1] = v.y; x[4 * c + 2] = v.z; x[4 * c + 3] = v.w;
    }
    float pA[16], pB[16], r[16], z[16];

    // r gate: accumulate both matvecs in partial space, single combine
    matvec_half<false>(x, s.Wih, q16, pA, pB);
    matvec_half<true>(h, s.Whh, q16, pA, pB);
    COMBINE_BIAS(r, pA, pB, s.bih + q16);
#pragma unroll
    for (int i = 0; i < 16; i++)
        r[i] = fast_sigmoid(r[i] + s.bhh[q16 + i]);

    // z gate
    matvec_half<false>(x, s.Wih + HH * DIMI, q16, pA, pB);
    matvec_half<true>(h, s.Whh + HH * HH, q16, pA, pB);
    COMBINE_BIAS(z, pA, pB, s.bih + HH + q16);
#pragma unroll
    for (int i = 0; i < 16; i++)
        z[i] = fast_sigmoid(z[i] + s.bhh[HH + q16 + i]);

    // n gate: gi and gh kept separate (r scales only the h-path)
    float gi[16], gh[16];
    matvec_half<false>(x, s.Wih + 2 * HH * DIMI, q16, pA, pB);
    COMBINE_BIAS(gi, pA, pB, s.bih + 2 * HH + q16);
    matvec_half<false>(h, s.Whh + 2 * HH * HH, q16, pA, pB);
    COMBINE_BIAS(gh, pA, pB, s.bhh + 2 * HH + q16);
#pragma unroll
    for (int i = 0; i < 16; i++) {
        float n = fast_tanh(gi[i] + r[i] * gh[i]);
        h[i] = (1.0f - z[i]) * n + z[i] * h[i];
    }
}

__device__ __forceinline__ void store_relu(float* __restrict__ dst,
                                           const float* __restrict__ y) {
    float4* d4 = (float4*)dst;
#pragma unroll
    for (int c = 0; c < 4; c++)
        d4[c] = make_float4(fmaxf(y[4 * c], 0.0f), fmaxf(y[4 * c + 1], 0.0f),
                            fmaxf(y[4 * c + 2], 0.0f), fmaxf(y[4 * c + 3], 0.0f));
}

__global__ void __launch_bounds__(128) ode_gru_kernel(
    const float* __restrict__ inputs,   // [B, 28, 32]
    const float* __restrict__ h0,       // [B, 32]
    const float* __restrict__ Wih, const float* __restrict__ Whh,
    const float* __restrict__ bih, const float* __restrict__ bhh,
    const float* __restrict__ W1,  const float* __restrict__ b1,
    const float* __restrict__ W2,  const float* __restrict__ b2,
    float* __restrict__ out)            // [2, B, 32]
{
    __shared__ SW s;
    const int tid = threadIdx.x;

    for (int i = tid; i < HH * HH; i += 128) { s.W1[i] = W1[i]; s.W2[i] = W2[i]; }
    for (int i = tid; i < 3 * HH * DIMI; i += 128) { s.Wih[i] = Wih[i]; s.Whh[i] = Whh[i]; }
    if (tid < HH)     { s.b1[tid]  = b1[tid];  s.b2[tid]  = b2[tid]; }
    if (tid < 3 * HH) { s.bih[tid] = bih[tid]; s.bhh[tid] = bhh[tid]; }
    __syncthreads();

    const int gt  = blockIdx.x * 128 + tid;  // 2 lanes per batch row
    const int row = gt >> 1;
    const int q16 = (gt & 1) * 16;           // this lane's element-half offset

    float y[16];
    const float4* h04 = (const float4*)(h0 + (size_t)row * HH + q16);
#pragma unroll
    for (int c = 0; c < 4; c++) {
        float4 v = h04[c];
        y[4 * c] = v.x; y[4 * c + 1] = v.y; y[4 * c + 2] = v.z; y[4 * c + 3] = v.w;
    }

    const float* xbase = inputs + (size_t)row * SEQT * DIMI + q16;

    rk4(y, 0.1f, q16, s);                         // initial span [0,1]
#pragma unroll 1
    for (int t = 0; t < SEQT - 1; t++) {          // steps 0..26
        gru(y, xbase + t * DIMI, q16, s);
        rk4(y, 0.1f, q16, s);
    }
    // step 27: GRU -> h_start, then span-14 integration -> h_end
    gru(y, xbase + (SEQT - 1) * DIMI, q16, s);
    store_relu(out + (size_t)row * HH + q16, y);
    rk4(y, 1.4f, q16, s);
    store_relu(out + ((size_t)BATCH + row) * HH + q16, y);
}

extern "C" void kernel_launch(void* const* d_in, const int* in_sizes, int n_in,
                              void* d_out, int out_size) {
    (void)in_sizes; (void)n_in; (void)out_size;
    ode_gru_kernel<<<(2 * BATCH) / 128, 128>>>(
        (const float*)d_in[0], (const float*)d_in[1],
        (const float*)d_in[2], (const float*)d_in[3],
        (const float*)d_in[4], (const float*)d_in[5],
        (const float*)d_in[6], (const float*)d_in[7],
        (const float*)d_in[8], (const float*)d_in[9],
        (float*)d_out);
}